// round 14
// baseline (speedup 1.0000x reference)
#include <cuda_runtime.h>
#include <cuda_bf16.h>
#include <cuda_fp16.h>
#include <cstdint>
#include <math.h>

#define B_ROWS 32768
#define R_N 4
#define U_N 256
#define D_N 256
#define NX 768  /* 3*U */
#define NZ 5
#define MG_N 128   /* M-tile PAIRS per z */
#define NT_N 6     /* N tiles: 768/128 */
#define KC8 8      /* K chunks of 32: 256/32 */

#if defined(__CUDA_ARCH__) && (defined(__CUDA_ARCH_FEAT_SM103_ALL) || \
    defined(__CUDA_ARCH_FEAT_SM100_ALL) || defined(__CUDA_ARCH_SPECIFIC__))
#define HAS_TCGEN05 1
#else
#define HAS_TCGEN05 0
#endif

// ---------------- global scratch (fp16 intermediates) ----------------
__device__ __half g_mx[(size_t)B_ROWS * NX];
__device__ __half g_inner[(size_t)B_ROWS * R_N * NX];

// Pre-swizzled SW64 bf16 W tiles: [z][nt][kc8], tile = 128 rows x 64B = 512 uint4
__device__ uint4 gW_hi[(size_t)NZ * NT_N * KC8 * 512];
__device__ uint4 gW_lo[(size_t)NZ * NT_N * KC8 * 512];

// ---------------- PTX helpers ----------------
static __device__ __forceinline__ uint32_t smem_u32(const void* p) {
    uint32_t a;
    asm("{ .reg .u64 t; cvta.to.shared.u64 t, %1; cvt.u32.u64 %0, t; }" : "=r"(a) : "l"(p));
    return a;
}
static __device__ __forceinline__ uint32_t elect1() {
    uint32_t p;
    asm volatile("{\n\t.reg .pred p;\n\telect.sync _|p, 0xFFFFFFFF;\n\tselp.b32 %0, 1, 0, p;\n\t}" : "=r"(p));
    return p;
}
// SW64: layout=4, version=1 (Blackwell), SBO=32 (512B atom), LBO=1 (16B inner)
#define SMEM_DESC_BASE_SW64 ((4ull<<61)|(1ull<<46)|(32ull<<32)|(1ull<<16))
static __device__ __forceinline__ uint64_t make_desc64(uint32_t addr) {
    return SMEM_DESC_BASE_SW64 | ((uint64_t)(addr >> 4) & 0x3FFFull);
}
#define IDESC_BF16 ((1u<<4)|(1u<<7)|(1u<<10)|((128u/8u)<<17)|((128u/16u)<<24))
#define SW64(byte) ((byte) ^ (((byte) >> 3) & 0x30u))

#define MBAR_INIT(addr, cnt) \
    asm volatile("mbarrier.init.shared.b64 [%0], %1;" :: "r"(addr), "r"(cnt) : "memory")
#define MBAR_INVAL(addr) \
    asm volatile("mbarrier.inval.shared.b64 [%0];" :: "r"(addr) : "memory")
#define MBAR_WAIT(addr, parity) do {                                              \
    uint32_t _m = (addr), _p = (parity), _d;                                      \
    asm volatile("{\n\t.reg .pred p;\n\t"                                         \
        "mbarrier.try_wait.parity.acquire.cta.shared::cta.b64 p, [%1], %2;\n\t"   \
        "selp.b32 %0, 1, 0, p;\n\t}" : "=r"(_d) : "r"(_m), "r"(_p) : "memory");   \
    if (!_d) {                                                                    \
        asm volatile("{\n\t.reg .pred P1;\n\t"                                    \
            "WL_%=:\n\t"                                                          \
            "mbarrier.try_wait.parity.acquire.cta.shared::cta.b64 P1, [%0], %1, 0x989680;\n\t" \
            "@P1 bra.uni WD_%=;\n\t"                                              \
            "bra.uni WL_%=;\n\t"                                                  \
            "WD_%=:\n\t}" :: "r"(_m), "r"(_p) : "memory");                        \
    } } while (0)

#if HAS_TCGEN05
static __device__ __forceinline__ void mma_f16_ss(uint32_t d_tmem, uint64_t a_desc,
                                                  uint64_t b_desc, uint32_t en) {
    asm volatile(
        "{\n\t"
        ".reg .pred p;\n\t"
        "setp.ne.u32 p, %4, 0;\n\t"
        "tcgen05.mma.cta_group::1.kind::f16 [%0], %1, %2, %3, {%5, %5, %5, %5}, p;\n\t"
        "}"
        :: "r"(d_tmem), "l"(a_desc), "l"(b_desc), "r"(IDESC_BF16), "r"(en), "r"(0u)
        : "memory");
}
#define TC_LD_X32(r, addr)                                                        \
    asm volatile("tcgen05.ld.sync.aligned.32x32b.x32.b32 "                        \
        "{%0, %1, %2, %3, %4, %5, %6, %7, "                                       \
        " %8, %9, %10, %11, %12, %13, %14, %15, "                                 \
        " %16, %17, %18, %19, %20, %21, %22, %23, "                               \
        " %24, %25, %26, %27, %28, %29, %30, %31}, [%32];"                        \
        : "=r"((r)[0]),  "=r"((r)[1]),  "=r"((r)[2]),  "=r"((r)[3]),              \
          "=r"((r)[4]),  "=r"((r)[5]),  "=r"((r)[6]),  "=r"((r)[7]),              \
          "=r"((r)[8]),  "=r"((r)[9]),  "=r"((r)[10]), "=r"((r)[11]),             \
          "=r"((r)[12]), "=r"((r)[13]), "=r"((r)[14]), "=r"((r)[15]),             \
          "=r"((r)[16]), "=r"((r)[17]), "=r"((r)[18]), "=r"((r)[19]),             \
          "=r"((r)[20]), "=r"((r)[21]), "=r"((r)[22]), "=r"((r)[23]),             \
          "=r"((r)[24]), "=r"((r)[25]), "=r"((r)[26]), "=r"((r)[27]),             \
          "=r"((r)[28]), "=r"((r)[29]), "=r"((r)[30]), "=r"((r)[31])              \
        : "r"(addr))
#endif

// ---------------- prep_W: fp32 -> bf16 hi/lo pre-swizzled SW64 tiles ----------------
// tile = [z][nt][kc8]: 128 N-rows x 32 k bf16 = 128 x 64B, SW64 swizzled.
__global__ void __launch_bounds__(256) prep_W(const float* __restrict__ kernelW,
                                              const float* __restrict__ rkernel) {
    unsigned i = blockIdx.x * 256u + threadIdx.x;   // < 240 tiles * 512 = 122880
    unsigned g    = i & 3u;                         // 16B group: 8 k-elems
    unsigned row  = (i >> 2) & 127u;                // N-row within tile
    unsigned tIdx = i >> 9;                         // (z*6+nt)*8 + kc
    unsigned kc   = tIdx & 7u;
    unsigned zn   = tIdx >> 3;
    unsigned z    = zn / 6u;
    unsigned nt   = zn % 6u;
    unsigned ncol = nt * 128u + row;
    unsigned hs[8], ls[8];
#pragma unroll
    for (int j = 0; j < 8; j++) {
        unsigned k = kc * 32u + g * 8u + j;
        float x = (z == 0) ? kernelW[(size_t)k * NX + ncol]
                           : rkernel[((size_t)(z - 1) * U_N + k) * NX + ncol];
        __nv_bfloat16 h = __float2bfloat16_rn(x);
        hs[j] = (unsigned)__bfloat16_as_ushort(h);
        ls[j] = (unsigned)__bfloat16_as_ushort(
            __float2bfloat16_rn(x - __bfloat162float(h)));
    }
    uint4 uh, ul;
    uh.x = hs[0] | (hs[1] << 16); uh.y = hs[2] | (hs[3] << 16);
    uh.z = hs[4] | (hs[5] << 16); uh.w = hs[6] | (hs[7] << 16);
    ul.x = ls[0] | (ls[1] << 16); ul.y = ls[2] | (ls[3] << 16);
    ul.z = ls[4] | (ls[5] << 16); ul.w = ls[6] | (ls[7] << 16);
    unsigned byte = row * 64u + g * 16u;
    unsigned sw = SW64(byte);
    gW_hi[(size_t)tIdx * 512 + (sw >> 4)] = uh;
    gW_lo[(size_t)tIdx * 512 + (sw >> 4)] = ul;
}

static __device__ __forceinline__ uint2 pack_half4(float4 f) {
    __half2 a = __floats2half2_rn(f.x, f.y);
    __half2 b = __floats2half2_rn(f.z, f.w);
    uint2 o;
    o.x = *(uint32_t*)&a;
    o.y = *(uint32_t*)&b;
    return o;
}

// ---------------- pipelined tcgen05 GEMM: K=32 steps, 2-stage, SW64 ----------------
// Stage (48KB): A0 hi 8K | A0 lo 8K | A1 hi 8K | A1 lo 8K | W hi 8K | W lo 8K
// Two stages at tb+0 / tb+49152. Epilogue staging (64KB) reuses tb+0.
#define STG_SZ 49152
#define DSMEM_BYTES 100352

__global__ void __launch_bounds__(256) gemm_tc(
    const float* __restrict__ inputs,
    const float* __restrict__ states,
    const float* __restrict__ kernelW,
    const float* __restrict__ rkernel,
    const float* __restrict__ bias)
{
    extern __shared__ __align__(16) char smem[];
    const uint32_t sb = smem_u32(smem);
    const int tid = threadIdx.x, wid = tid >> 5, lane = tid & 31;
    const int nt = blockIdx.x, mtg = blockIdx.y, z = blockIdx.z;
    const int mt0 = mtg * 2;

    const uint32_t tb = (sb + 1024u + 1023u) & ~1023u;
    char* tbp = smem + (tb - sb);
    const uint32_t bar0 = sb + 8;   // 8 one-shot barriers, 8B apart

    const int lda = (z == 0) ? D_N : (R_N * U_N);
    const float* Abase = (z == 0) ? inputs : (states + (z - 1) * U_N);

#if HAS_TCGEN05
    if (wid == 0) {
        asm volatile("tcgen05.alloc.cta_group::1.sync.aligned.shared::cta.b32 [%0], %1;"
                     :: "r"(sb), "r"(256u) : "memory");
        asm volatile("tcgen05.relinquish_alloc_permit.cta_group::1.sync.aligned;");
    }
    if (tid == 0) {
        for (int i2 = 0; i2 < KC8; i2++) MBAR_INIT(bar0 + 8 * i2, 1u);
    }
    asm volatile("fence.proxy.async.shared::cta;" ::: "memory");
    __syncthreads();
    uint32_t tmem;
    asm volatile("ld.shared.b32 %0, [%1];" : "=r"(tmem) : "r"(sb));

    // A-load coords: g4 = 16B bf16 group (8 k), row = tid>>2 (64 rows/pass, 2 passes)
    const unsigned g4 = (unsigned)(tid & 3);
    const unsigned arw = (unsigned)(tid >> 2);

    for (int s = 0; s < KC8; s++) {
        const int buf = s & 1;
        // One-shot: bar[s-2] receives exactly one commit; wait(0) <=> done. Exact.
        if (s >= 2) MBAR_WAIT(bar0 + 8 * (s - 2), 0u);
        char* stg = tbp + buf * STG_SZ;
        // ---- A both tiles: fp32 -> bf16 hi/lo, SW64 ----
#pragma unroll
        for (int t = 0; t < 2; t++) {
            uint4* sAh = (uint4*)(stg + t * 16384);
            uint4* sAl = (uint4*)(stg + t * 16384 + 8192);
            const float* srcb = Abase + (size_t)((mt0 + t) * 128) * lda + s * 32 + g4 * 8;
#pragma unroll
            for (int j = 0; j < 2; j++) {
                unsigned row = arw + j * 64;
                const float* src = srcb + (size_t)row * lda;
                float4 f0 = *(const float4*)src;
                float4 f1 = *(const float4*)(src + 4);
                float x[8] = {f0.x, f0.y, f0.z, f0.w, f1.x, f1.y, f1.z, f1.w};
                unsigned hs[8], lsv[8];
#pragma unroll
                for (int e = 0; e < 8; e++) {
                    __nv_bfloat16 h = __float2bfloat16_rn(x[e]);
                    hs[e] = (unsigned)__bfloat16_as_ushort(h);
                    lsv[e] = (unsigned)__bfloat16_as_ushort(
                        __float2bfloat16_rn(x[e] - __bfloat162float(h)));
                }
                uint4 uh, ul;
                uh.x = hs[0] | (hs[1] << 16); uh.y = hs[2] | (hs[3] << 16);
                uh.z = hs[4] | (hs[5] << 16); uh.w = hs[6] | (hs[7] << 16);
                ul.x = lsv[0] | (lsv[1] << 16); ul.y = lsv[2] | (lsv[3] << 16);
                ul.z = lsv[4] | (lsv[5] << 16); ul.w = lsv[6] | (lsv[7] << 16);
                unsigned byte = row * 64u + g4 * 16u;
                unsigned sw = SW64(byte);
                sAh[sw >> 4] = uh;
                sAl[sw >> 4] = ul;
            }
        }
        // ---- W: identity copies of pre-swizzled SW64 tiles ----
        {
            const size_t tB = ((size_t)((z * NT_N + nt) * KC8 + s)) * 512;
            uint4* sWh = (uint4*)(stg + 32768);
            uint4* sWl = (uint4*)(stg + 40960);
#pragma unroll
            for (int j = 0; j < 2; j++) {
                int idx = tid + j * 256;
                sWh[idx] = gW_hi[tB + idx];
                sWl[idx] = gW_lo[tB + idx];
            }
        }
        asm volatile("fence.proxy.async.shared::cta;" ::: "memory");
        __syncthreads();
        if (wid == 0 && elect1()) {
            const uint32_t stgb = tb + buf * STG_SZ;
            const uint64_t dBh = make_desc64(stgb + 32768);
            const uint64_t dBl = make_desc64(stgb + 40960);
#pragma unroll
            for (int t = 0; t < 2; t++) {
                const uint32_t dz = tmem + (unsigned)(t * 128);
                const uint64_t dAh = make_desc64(stgb + t * 16384);
                const uint64_t dAl = make_desc64(stgb + t * 16384 + 8192);
#pragma unroll
                for (int ks = 0; ks < 2; ks++) {
                    uint64_t off = (uint64_t)(ks * 2);
                    mma_f16_ss(dz, dAh + off, dBh + off, (s == 0 && ks == 0) ? 0u : 1u);
                    mma_f16_ss(dz, dAh + off, dBl + off, 1u);
                    mma_f16_ss(dz, dAl + off, dBh + off, 1u);
                }
            }
            asm volatile(
                "tcgen05.commit.cta_group::1.mbarrier::arrive::one.shared::cluster.b64 [%0];"
                :: "r"(bar0 + 8 * s) : "memory");
        }
    }
    // Drain: bar[7] one-shot; its commit covers ALL previously issued MMAs.
    MBAR_WAIT(bar0 + 8 * (KC8 - 1), 0u);
    asm volatile("tcgen05.fence::after_thread_sync;" ::: "memory");

    // ---- epilogue per M-tile: TMEM -> swizzled stage -> coalesced fp16 global ----
    const int cb = (wid >> 2) * 64;
    const int row = (wid & 3) * 32 + lane;
    const int n0 = nt * 128;
#pragma unroll 1
    for (int t = 0; t < 2; t++) {
        const uint32_t dcol = (unsigned)(t * 128);
#pragma unroll
        for (int half = 0; half < 2; half++) {
            uint32_t r[32];
            TC_LD_X32(r, tmem + dcol + (uint32_t)(cb + half * 32));
            asm volatile("tcgen05.wait::ld.sync.aligned;" ::: "memory");
#pragma unroll
            for (int q = 0; q < 8; q++) {
                int col = cb + half * 32 + q * 4;
                unsigned byte = (unsigned)row * 512u + (unsigned)col * 4u;
                unsigned phys = byte ^ (((unsigned)row & 7u) << 4);
                *(uint4*)(tbp + phys) = make_uint4(r[q*4+0], r[q*4+1], r[q*4+2], r[q*4+3]);
            }
        }
        __syncthreads();
#pragma unroll
        for (int it = 0; it < 16; it++) {
            int i2 = tid + it * 256;
            int rw = i2 >> 5, c4 = i2 & 31;
            unsigned byte = (unsigned)rw * 512u + (unsigned)c4 * 16u;
            unsigned phys = byte ^ (((unsigned)rw & 7u) << 4);
            uint4 v = *(const uint4*)(tbp + phys);
            float4 f;
            f.x = __uint_as_float(v.x); f.y = __uint_as_float(v.y);
            f.z = __uint_as_float(v.z); f.w = __uint_as_float(v.w);
            const float4 b4 = *(const float4*)(bias + (size_t)z * NX + n0 + c4 * 4);
            f.x += b4.x; f.y += b4.y; f.z += b4.z; f.w += b4.w;
            size_t rg = (size_t)(mt0 + t) * 128 + rw;
            __half* dst = (z == 0)
                ? (g_mx + rg * NX + n0 + c4 * 4)
                : (g_inner + rg * (R_N * NX) + (size_t)(z - 1) * NX + n0 + c4 * 4);
            *(uint2*)dst = pack_half4(f);
        }
        __syncthreads();
    }
    if (tid == 0) {
        for (int i2 = 0; i2 < KC8; i2++) MBAR_INVAL(bar0 + 8 * i2);
    }
    __syncthreads();
    if (wid == 0) {
        asm volatile("tcgen05.dealloc.cta_group::1.sync.aligned.b32 %0, %1;"
                     :: "r"(tmem), "r"(256u));
    }
#else
    // fp32 fallback (generic PTX pass only; never executed with sm_103a cubin)
    __syncthreads();
    for (int t = 0; t < 2; t++) {
        const int mt = mt0 + t;
        const int frow = tid >> 1;
        const int fc0 = (tid & 1) * 64;
        float facc[64];
        for (int j = 0; j < 64; j++) facc[j] = 0.f;
        for (int k = 0; k < D_N; k++) {
            float a = Abase[(size_t)(mt * 128 + frow) * lda + k];
            for (int j = 0; j < 64; j++) {
                int ncol = nt * 128 + fc0 + j;
                float wv = (z == 0) ? kernelW[(size_t)k * NX + ncol]
                                    : rkernel[((size_t)(z - 1) * U_N + k) * NX + ncol];
                facc[j] = fmaf(a, wv, facc[j]);
            }
        }
        size_t rg = (size_t)mt * 128 + frow;
        const int n0f = nt * 128;
        for (int j = 0; j < 64; j++) {
            float f = facc[j] + bias[(size_t)z * NX + n0f + fc0 + j];
            __half* dst = (z == 0)
                ? (g_mx + rg * NX + n0f + fc0 + j)
                : (g_inner + rg * (R_N * NX) + (size_t)(z - 1) * NX + n0f + fc0 + j);
            *dst = __float2half_rn(f);
        }
    }
#endif
}

// ---------------- vectorized fused epilogue (unchanged from R13 pass) ----------------
static __device__ __forceinline__ float4 ld4(const float* p) { return *(const float4*)p; }
static __device__ __forceinline__ float4 ld4h(const __half* p) {
    uint2 u = *(const uint2*)p;
    __half2 a = *(__half2*)&u.x;
    __half2 b = *(__half2*)&u.y;
    float4 f;
    f.x = __low2float(a); f.y = __high2float(a);
    f.z = __low2float(b); f.w = __high2float(b);
    return f;
}
static __device__ __forceinline__ float fast_sigmoid(float x) {
    return 1.0f / (1.0f + __expf(-x));
}
static __device__ __forceinline__ float fast_tanh(float x) {
    return 2.0f / (1.0f + __expf(-2.0f * x)) - 1.0f;
}

__global__ void __launch_bounds__(256) fuse_kernel(
    const float* __restrict__ states,
    const int* __restrict__ cell_mask,
    const float* __restrict__ v,
    float* __restrict__ out)
{
    const int rin = threadIdx.x >> 6;
    const int b = blockIdx.x * 4 + rin;
    const int t = threadIdx.x & 63;
    const int u0 = t * 4;

    const __half* mxp = g_mx + (size_t)b * NX;
    const float4 xz = ld4h(mxp + u0);
    const float4 xr = ld4h(mxp + U_N + u0);
    const float4 xh = ld4h(mxp + 2 * U_N + u0);

    bool m[R_N];
#pragma unroll
    for (int r = 0; r < R_N; r++) m[r] = cell_mask[b * R_N + r] != 0;

    float4 rz[R_N];
    float4 acc = make_float4(0.f, 0.f, 0.f, 0.f);
#pragma unroll
    for (int r = 0; r < R_N; r++) {
        const __half* ip = g_inner + (size_t)b * (R_N * NX) + (size_t)r * NX;
        rz[r] = ld4h(ip + u0);
        const float4 rr  = ld4h(ip + U_N + u0);
        const float4 rhc = ld4h(ip + 2 * U_N + u0);
        if (m[r]) {
            acc.x += rhc.x * fast_sigmoid(xr.x + rr.x);
            acc.y += rhc.y * fast_sigmoid(xr.y + rr.y);
            acc.z += rhc.z * fast_sigmoid(xr.z + rr.z);
            acc.w += rhc.w * fast_sigmoid(xr.w + rr.w);
        }
    }
    float4 hh;
    hh.x = fast_tanh(xh.x + acc.x * 0.25f);
    hh.y = fast_tanh(xh.y + acc.y * 0.25f);
    hh.z = fast_tanh(xh.z + acc.z * 0.25f);
    hh.w = fast_tanh(xh.w + acc.w * 0.25f);

    const float4 vv = ld4(v + u0);
    float part[R_N + 1];
#pragma unroll
    for (int r = 0; r < R_N; r++) {
        part[r] = fast_tanh(xz.x + rz[r].x) * vv.x + fast_tanh(xz.y + rz[r].y) * vv.y
                + fast_tanh(xz.z + rz[r].z) * vv.z + fast_tanh(xz.w + rz[r].w) * vv.w;
    }
    part[R_N] = fast_tanh(xz.x + hh.x) * vv.x + fast_tanh(xz.y + hh.y) * vv.y
              + fast_tanh(xz.z + hh.z) * vv.z + fast_tanh(xz.w + hh.w) * vv.w;

    __shared__ float wsum[8][R_N + 1];
    const int warp = threadIdx.x >> 5;
    const int lane = threadIdx.x & 31;
#pragma unroll
    for (int k = 0; k < R_N + 1; k++) {
        float s = part[k];
#pragma unroll
        for (int off = 16; off > 0; off >>= 1)
            s += __shfl_down_sync(0xffffffffu, s, off);
        if (lane == 0) wsum[warp][k] = s;
    }
    __shared__ float prob_s[4][R_N + 1];
    __syncthreads();
    if (t == 0) {
        float logit[R_N + 1];
        float mx = -INFINITY;
#pragma unroll
        for (int k = 0; k < R_N + 1; k++) {
            float s = wsum[rin * 2][k] + wsum[rin * 2 + 1][k];
            const bool ok = (k == R_N) ? true : m[k];
            logit[k] = ok ? s : -INFINITY;
            mx = fmaxf(mx, logit[k]);
        }
        float denom = 0.f;
        float e[R_N + 1];
#pragma unroll
        for (int k = 0; k < R_N + 1; k++) {
            e[k] = (logit[k] == -INFINITY) ? 0.f : __expf(logit[k] - mx);
            denom += e[k];
        }
#pragma unroll
        for (int k = 0; k < R_N + 1; k++) prob_s[rin][k] = e[k] / denom;
    }
    __syncthreads();

    float4 h = make_float4(0.f, 0.f, 0.f, 0.f);
#pragma unroll
    for (int r = 0; r < R_N; r++) {
        const float4 st = ld4(states + (size_t)b * (R_N * U_N) + r * U_N + u0);
        const float p = prob_s[rin][r];
        h.x += st.x * p; h.y += st.y * p; h.z += st.z * p; h.w += st.w * p;
    }
    const float p4 = prob_s[rin][R_N];
    h.x += hh.x * p4; h.y += hh.y * p4; h.z += hh.z * p4; h.w += hh.w * p4;
    *(float4*)(out + (size_t)b * U_N + u0) = h;
}

extern "C" void kernel_launch(void* const* d_in, const int* in_sizes, int n_in,
                              void* d_out, int out_size) {
    const float* inputs    = (const float*)d_in[0];
    const float* states    = (const float*)d_in[1];
    /* d_in[2] = edge_types (dead in reference) */
    const int*   cell_mask = (const int*)d_in[3];
    const float* kernelW   = (const float*)d_in[4];
    const float* rkernel   = (const float*)d_in[5];
    const float* bias      = (const float*)d_in[6];
    const float* v         = (const float*)d_in[7];
    /* d_in[8] = edge_emb (dead in reference) */
    float* out = (float*)d_out;
    (void)in_sizes; (void)n_in; (void)out_size;

    cudaFuncSetAttribute(gemm_tc, cudaFuncAttributeMaxDynamicSharedMemorySize, DSMEM_BYTES);

    prep_W<<<480, 256>>>(kernelW, rkernel);
    gemm_tc<<<dim3(NT_N, MG_N, NZ), 256, DSMEM_BYTES>>>(
        inputs, states, kernelW, rkernel, bias);
    fuse_kernel<<<B_ROWS / 4, 256>>>(states, cell_mask, v, out);
}

// round 15
// speedup vs baseline: 1.0195x; 1.0195x over previous
#include <cuda_runtime.h>
#include <cuda_bf16.h>
#include <cuda_fp16.h>
#include <cstdint>
#include <math.h>

#define B_ROWS 32768
#define R_N 4
#define U_N 256
#define D_N 256
#define NX 768  /* 3*U */
#define NZ 5
#define MG_N 128   /* M-tile PAIRS per z */
#define NT_N 6     /* N tiles: 768/128 */
#define KC_N 4     /* K chunks: 256/64 */

#if defined(__CUDA_ARCH__) && (defined(__CUDA_ARCH_FEAT_SM103_ALL) || \
    defined(__CUDA_ARCH_FEAT_SM100_ALL) || defined(__CUDA_ARCH_SPECIFIC__))
#define HAS_TCGEN05 1
#else
#define HAS_TCGEN05 0
#endif

// ---------------- global scratch (fp16 intermediates) ----------------
__device__ __half g_mx[(size_t)B_ROWS * NX];
__device__ __half g_inner[(size_t)B_ROWS * R_N * NX];

// Pre-swizzled bf16 W tiles, [z][nt][kc], tile = 128 rows x 128B SW128 = 1024 uint4
__device__ uint4 gW_hi[(size_t)NZ * NT_N * KC_N * 1024];
__device__ uint4 gW_lo[(size_t)NZ * NT_N * KC_N * 1024];

// ---------------- PTX helpers ----------------
static __device__ __forceinline__ uint32_t smem_u32(const void* p) {
    uint32_t a;
    asm("{ .reg .u64 t; cvta.to.shared.u64 t, %1; cvt.u32.u64 %0, t; }" : "=r"(a) : "l"(p));
    return a;
}
static __device__ __forceinline__ uint32_t elect1() {
    uint32_t p;
    asm volatile("{\n\t.reg .pred p;\n\telect.sync _|p, 0xFFFFFFFF;\n\tselp.b32 %0, 1, 0, p;\n\t}" : "=r"(p));
    return p;
}
#define SMEM_DESC_BASE ((2ull<<61)|(1ull<<46)|(64ull<<32)|(1ull<<16))
static __device__ __forceinline__ uint64_t make_desc(uint32_t addr) {
    return SMEM_DESC_BASE | ((uint64_t)(addr >> 4) & 0x3FFFull);
}
#define IDESC_BF16 ((1u<<4)|(1u<<7)|(1u<<10)|((128u/8u)<<17)|((128u/16u)<<24))

#define MBAR_INIT(addr, cnt) \
    asm volatile("mbarrier.init.shared.b64 [%0], %1;" :: "r"(addr), "r"(cnt) : "memory")
#define MBAR_INVAL(addr) \
    asm volatile("mbarrier.inval.shared.b64 [%0];" :: "r"(addr) : "memory")
#define MBAR_WAIT(addr, parity) do {                                              \
    uint32_t _m = (addr), _p = (parity), _d;                                      \
    asm volatile("{\n\t.reg .pred p;\n\t"                                         \
        "mbarrier.try_wait.parity.acquire.cta.shared::cta.b64 p, [%1], %2;\n\t"   \
        "selp.b32 %0, 1, 0, p;\n\t}" : "=r"(_d) : "r"(_m), "r"(_p) : "memory");   \
    if (!_d) {                                                                    \
        asm volatile("{\n\t.reg .pred P1;\n\t"                                    \
            "WL_%=:\n\t"                                                          \
            "mbarrier.try_wait.parity.acquire.cta.shared::cta.b64 P1, [%0], %1, 0x989680;\n\t" \
            "@P1 bra.uni WD_%=;\n\t"                                              \
            "bra.uni WL_%=;\n\t"                                                  \
            "WD_%=:\n\t}" :: "r"(_m), "r"(_p) : "memory");                        \
    } } while (0)

#if HAS_TCGEN05
static __device__ __forceinline__ void mma_f16_ss(uint32_t d_tmem, uint64_t a_desc,
                                                  uint64_t b_desc, uint32_t en) {
    asm volatile(
        "{\n\t"
        ".reg .pred p;\n\t"
        "setp.ne.u32 p, %4, 0;\n\t"
        "tcgen05.mma.cta_group::1.kind::f16 [%0], %1, %2, %3, {%5, %5, %5, %5}, p;\n\t"
        "}"
        :: "r"(d_tmem), "l"(a_desc), "l"(b_desc), "r"(IDESC_BF16), "r"(en), "r"(0u)
        : "memory");
}
#define TC_LD_X32(r, addr)                                                        \
    asm volatile("tcgen05.ld.sync.aligned.32x32b.x32.b32 "                        \
        "{%0, %1, %2, %3, %4, %5, %6, %7, "                                       \
        " %8, %9, %10, %11, %12, %13, %14, %15, "                                 \
        " %16, %17, %18, %19, %20, %21, %22, %23, "                               \
        " %24, %25, %26, %27, %28, %29, %30, %31}, [%32];"                        \
        : "=r"((r)[0]),  "=r"((r)[1]),  "=r"((r)[2]),  "=r"((r)[3]),              \
          "=r"((r)[4]),  "=r"((r)[5]),  "=r"((r)[6]),  "=r"((r)[7]),              \
          "=r"((r)[8]),  "=r"((r)[9]),  "=r"((r)[10]), "=r"((r)[11]),             \
          "=r"((r)[12]), "=r"((r)[13]), "=r"((r)[14]), "=r"((r)[15]),             \
          "=r"((r)[16]), "=r"((r)[17]), "=r"((r)[18]), "=r"((r)[19]),             \
          "=r"((r)[20]), "=r"((r)[21]), "=r"((r)[22]), "=r"((r)[23]),             \
          "=r"((r)[24]), "=r"((r)[25]), "=r"((r)[26]), "=r"((r)[27]),             \
          "=r"((r)[28]), "=r"((r)[29]), "=r"((r)[30]), "=r"((r)[31])              \
        : "r"(addr))
#endif

// ---------------- prep_W: fp32 -> bf16 hi/lo pre-swizzled W tiles ----------------
__global__ void __launch_bounds__(256) prep_W(const float* __restrict__ kernelW,
                                              const float* __restrict__ rkernel) {
    unsigned i = blockIdx.x * 256u + threadIdx.x;      // < 122880
    unsigned g   = i & 7u;
    unsigned nr  = (i >> 3) & 127u;
    unsigned top = i >> 10;           // (z*6+nt)*4+kc
    unsigned kc  = top & 3u;
    unsigned tz  = top >> 2;
    unsigned z   = tz / 6u;
    unsigned nt  = tz % 6u;
    unsigned ncol = nt * 128u + nr;
    unsigned hs[8], ls[8];
#pragma unroll
    for (int j = 0; j < 8; j++) {
        unsigned k = kc * 64u + g * 8u + j;
        float x = (z == 0) ? kernelW[(size_t)k * NX + ncol]
                           : rkernel[((size_t)(z - 1) * U_N + k) * NX + ncol];
        __nv_bfloat16 h = __float2bfloat16_rn(x);
        hs[j] = (unsigned)__bfloat16_as_ushort(h);
        float hf = __bfloat162float(h);
        ls[j] = (unsigned)__bfloat16_as_ushort(__float2bfloat16_rn(x - hf));
    }
    uint4 uh, ul;
    uh.x = hs[0] | (hs[1] << 16); uh.y = hs[2] | (hs[3] << 16);
    uh.z = hs[4] | (hs[5] << 16); uh.w = hs[6] | (hs[7] << 16);
    ul.x = ls[0] | (ls[1] << 16); ul.y = ls[2] | (ls[3] << 16);
    ul.z = ls[4] | (ls[5] << 16); ul.w = ls[6] | (ls[7] << 16);
    unsigned byte = (nr * 8u + g) * 16u;
    unsigned sw = byte ^ ((byte >> 3) & 0x70u);
    gW_hi[(size_t)top * 1024 + (sw >> 4)] = uh;
    gW_lo[(size_t)top * 1024 + (sw >> 4)] = ul;
}

static __device__ __forceinline__ uint2 pack_half4(float4 f) {
    __half2 a = __floats2half2_rn(f.x, f.y);
    __half2 b = __floats2half2_rn(f.z, f.w);
    uint2 o;
    o.x = *(uint32_t*)&a;
    o.y = *(uint32_t*)&b;
    return o;
}

// ---------------- tcgen05 GEMM: 2 M-tiles/CTA + register-staged prefetch ----------------
// SMEM from tb (1024-aligned): A0 hi/lo 32K | A1 hi/lo 32K | W hi/lo 32K = 96K
#define SM_A0 0
#define SM_A1 32768
#define SM_W  65536
#define DSMEM_BYTES 99328

__global__ void __launch_bounds__(256, 2) gemm_tc(
    const float* __restrict__ inputs,
    const float* __restrict__ states,
    const float* __restrict__ kernelW,
    const float* __restrict__ rkernel,
    const float* __restrict__ bias)
{
    extern __shared__ __align__(16) char smem[];
    const uint32_t sb = smem_u32(smem);
    const int tid = threadIdx.x, wid = tid >> 5, lane = tid & 31;
    const int nt = blockIdx.x, mtg = blockIdx.y, z = blockIdx.z;
    const int mt0 = mtg * 2;

    const uint32_t tb = (sb + 1024u + 1023u) & ~1023u;
    char* tbp = smem + (tb - sb);

    const int lda = (z == 0) ? D_N : (R_N * U_N);
    const float* Abase = (z == 0) ? inputs : (states + (z - 1) * U_N);

#if HAS_TCGEN05
    if (wid == 0) {
        asm volatile("tcgen05.alloc.cta_group::1.sync.aligned.shared::cta.b32 [%0], %1;"
                     :: "r"(sb), "r"(256u) : "memory");
        asm volatile("tcgen05.relinquish_alloc_permit.cta_group::1.sync.aligned;");
    }
    if (tid == 0) MBAR_INIT(sb + 8, 1u);
    __syncthreads();
    uint32_t tmem;
    asm volatile("ld.shared.b32 %0, [%1];" : "=r"(tmem) : "r"(sb));

    const unsigned g8 = (unsigned)(tid & 7);     // 16B-group within 64-float row
    const unsigned arw = (unsigned)(tid >> 3);   // row base, 32 rows per pass
    const size_t wTileBase = ((size_t)((z * NT_N + nt) * KC_N)) * 1024;

    // register staging: A raw fp32 (16 x float4), W pre-swizzled (8 x uint4)
    float4 pa[16];
    uint4  pw[8];

    // prologue: issue loads for kc = 0
#pragma unroll
    for (int t = 0; t < 2; t++) {
        const float* srcb = Abase + (size_t)((mt0 + t) * 128) * lda + g8 * 8;
#pragma unroll
        for (int j = 0; j < 4; j++) {
            const float* src = srcb + (size_t)(arw + j * 32) * lda;
            pa[t * 8 + j * 2 + 0] = *(const float4*)src;
            pa[t * 8 + j * 2 + 1] = *(const float4*)(src + 4);
        }
    }
#pragma unroll
    for (int j = 0; j < 4; j++) {
        pw[j]     = gW_hi[wTileBase + tid + j * 256];
        pw[4 + j] = gW_lo[wTileBase + tid + j * 256];
    }

    for (int kc = 0; kc < KC_N; kc++) {
        // Full-drain lag-1 protocol (proven R4/R7/R12/R13): exact.
        if (kc > 0) MBAR_WAIT(sb + 8, (unsigned)((kc - 1) & 1));
        // ---- convert + store prefetched A (hi/lo split), store W ----
#pragma unroll
        for (int t = 0; t < 2; t++) {
            uint4* sAh = (uint4*)(tbp + (t ? SM_A1 : SM_A0));
            uint4* sAl = (uint4*)(tbp + (t ? SM_A1 : SM_A0) + 16384);
#pragma unroll
            for (int j = 0; j < 4; j++) {
                float4 f0 = pa[t * 8 + j * 2 + 0];
                float4 f1 = pa[t * 8 + j * 2 + 1];
                float x[8] = {f0.x, f0.y, f0.z, f0.w, f1.x, f1.y, f1.z, f1.w};
                unsigned hs[8], lsv[8];
#pragma unroll
                for (int e = 0; e < 8; e++) {
                    __nv_bfloat16 h = __float2bfloat16_rn(x[e]);
                    hs[e] = (unsigned)__bfloat16_as_ushort(h);
                    lsv[e] = (unsigned)__bfloat16_as_ushort(
                        __float2bfloat16_rn(x[e] - __bfloat162float(h)));
                }
                uint4 uh, ul;
                uh.x = hs[0] | (hs[1] << 16); uh.y = hs[2] | (hs[3] << 16);
                uh.z = hs[4] | (hs[5] << 16); uh.w = hs[6] | (hs[7] << 16);
                ul.x = lsv[0] | (lsv[1] << 16); ul.y = lsv[2] | (lsv[3] << 16);
                ul.z = lsv[4] | (lsv[5] << 16); ul.w = lsv[6] | (lsv[7] << 16);
                unsigned byte = (arw + j * 32) * 128u + g8 * 16u;
                unsigned sw = byte ^ ((byte >> 3) & 0x70u);
                sAh[sw >> 4] = uh;
                sAl[sw >> 4] = ul;
            }
        }
        {
            uint4* sWh = (uint4*)(tbp + SM_W);
            uint4* sWl = (uint4*)(tbp + SM_W + 16384);
#pragma unroll
            for (int j = 0; j < 4; j++) {
                sWh[tid + j * 256] = pw[j];
                sWl[tid + j * 256] = pw[4 + j];
            }
        }
        asm volatile("fence.proxy.async.shared::cta;" ::: "memory");
        __syncthreads();
        // ---- MMAs ----
        if (wid == 0 && elect1()) {
            const uint64_t dBh = make_desc(tb + SM_W);
            const uint64_t dBl = make_desc(tb + SM_W + 16384);
#pragma unroll
            for (int t = 0; t < 2; t++) {
                const uint32_t dz = tmem + (unsigned)(t * 128);
                const uint64_t dAh = make_desc(tb + (t ? SM_A1 : SM_A0));
                const uint64_t dAl = make_desc(tb + (t ? SM_A1 : SM_A0) + 16384);
#pragma unroll
                for (int ks = 0; ks < 4; ks++) {
                    uint64_t off = (uint64_t)(ks * 2);
                    mma_f16_ss(dz, dAh + off, dBh + off, (kc == 0 && ks == 0) ? 0u : 1u);
                    mma_f16_ss(dz, dAh + off, dBl + off, 1u);
                    mma_f16_ss(dz, dAl + off, dBh + off, 1u);
                }
            }
            asm volatile(
                "tcgen05.commit.cta_group::1.mbarrier::arrive::one.shared::cluster.b64 [%0];"
                :: "r"(sb + 8) : "memory");
        }
        // ---- prefetch next step's A + W into registers (overlaps MMA) ----
        if (kc + 1 < KC_N) {
            const int kn = kc + 1;
#pragma unroll
            for (int t = 0; t < 2; t++) {
                const float* srcb = Abase + (size_t)((mt0 + t) * 128) * lda + kn * 64 + g8 * 8;
#pragma unroll
                for (int j = 0; j < 4; j++) {
                    const float* src = srcb + (size_t)(arw + j * 32) * lda;
                    pa[t * 8 + j * 2 + 0] = *(const float4*)src;
                    pa[t * 8 + j * 2 + 1] = *(const float4*)(src + 4);
                }
            }
            const size_t tB = wTileBase + (size_t)kn * 1024;
#pragma unroll
            for (int j = 0; j < 4; j++) {
                pw[j]     = gW_hi[tB + tid + j * 256];
                pw[4 + j] = gW_lo[tB + tid + j * 256];
            }
        }
    }
    MBAR_WAIT(sb + 8, 1u);   // 4 commits -> exact (c=4)
    asm volatile("tcgen05.fence::after_thread_sync;" ::: "memory");

    // ---- epilogue per M-tile: TMEM -> swizzled stage -> coalesced fp16 global ----
    const int cb = (wid >> 2) * 64;
    const int row = (wid & 3) * 32 + lane;
    const int n0 = nt * 128;
#pragma unroll 1
    for (int t = 0; t < 2; t++) {
        const uint32_t dcol = (unsigned)(t * 128);
#pragma unroll
        for (int half = 0; half < 2; half++) {
            uint32_t r[32];
            TC_LD_X32(r, tmem + dcol + (uint32_t)(cb + half * 32));
            asm volatile("tcgen05.wait::ld.sync.aligned;" ::: "memory");
#pragma unroll
            for (int q = 0; q < 8; q++) {
                int col = cb + half * 32 + q * 4;
                unsigned byte = (unsigned)row * 512u + (unsigned)col * 4u;
                unsigned phys = byte ^ (((unsigned)row & 7u) << 4);
                *(uint4*)(tbp + phys) = make_uint4(r[q*4+0], r[q*4+1], r[q*4+2], r[q*4+3]);
            }
        }
        __syncthreads();
#pragma unroll
        for (int it = 0; it < 16; it++) {
            int i2 = tid + it * 256;
            int rw = i2 >> 5, c4 = i2 & 31;
            unsigned byte = (unsigned)rw * 512u + (unsigned)c4 * 16u;
            unsigned phys = byte ^ (((unsigned)rw & 7u) << 4);
            uint4 v = *(const uint4*)(tbp + phys);
            float4 f;
            f.x = __uint_as_float(v.x); f.y = __uint_as_float(v.y);
            f.z = __uint_as_float(v.z); f.w = __uint_as_float(v.w);
            const float4 b4 = *(const float4*)(bias + (size_t)z * NX + n0 + c4 * 4);
            f.x += b4.x; f.y += b4.y; f.z += b4.z; f.w += b4.w;
            size_t rg = (size_t)(mt0 + t) * 128 + rw;
            __half* dst = (z == 0)
                ? (g_mx + rg * NX + n0 + c4 * 4)
                : (g_inner + rg * (R_N * NX) + (size_t)(z - 1) * NX + n0 + c4 * 4);
            *(uint2*)dst = pack_half4(f);
        }
        __syncthreads();
    }
    if (tid == 0) MBAR_INVAL(sb + 8);
    __syncthreads();
    if (wid == 0) {
        asm volatile("tcgen05.dealloc.cta_group::1.sync.aligned.b32 %0, %1;"
                     :: "r"(tmem), "r"(256u));
    }
#else
    // fp32 fallback (generic PTX pass only; never executed with sm_103a cubin)
    __syncthreads();
    for (int t = 0; t < 2; t++) {
        const int mt = mt0 + t;
        const int frow = tid >> 1;
        const int fc0 = (tid & 1) * 64;
        float facc[64];
        for (int j = 0; j < 64; j++) facc[j] = 0.f;
        for (int k = 0; k < D_N; k++) {
            float a = Abase[(size_t)(mt * 128 + frow) * lda + k];
            for (int j = 0; j < 64; j++) {
                int ncol = nt * 128 + fc0 + j;
                float wv = (z == 0) ? kernelW[(size_t)k * NX + ncol]
                                    : rkernel[((size_t)(z - 1) * U_N + k) * NX + ncol];
                facc[j] = fmaf(a, wv, facc[j]);
            }
        }
        size_t rg = (size_t)mt * 128 + frow;
        const int n0f = nt * 128;
        for (int j = 0; j < 64; j++) {
            float f = facc[j] + bias[(size_t)z * NX + n0f + fc0 + j];
            __half* dst = (z == 0)
                ? (g_mx + rg * NX + n0f + fc0 + j)
                : (g_inner + rg * (R_N * NX) + (size_t)(z - 1) * NX + n0f + fc0 + j);
            *dst = __float2half_rn(f);
        }
    }
#endif
}

// ---------------- vectorized fused epilogue (unchanged from R13 pass) ----------------
static __device__ __forceinline__ float4 ld4(const float* p) { return *(const float4*)p; }
static __device__ __forceinline__ float4 ld4h(const __half* p) {
    uint2 u = *(const uint2*)p;
    __half2 a = *(__half2*)&u.x;
    __half2 b = *(__half2*)&u.y;
    float4 f;
    f.x = __low2float(a); f.y = __high2float(a);
    f.z = __low2float(b); f.w = __high2float(b);
    return f;
}
static __device__ __forceinline__ float fast_sigmoid(float x) {
    return 1.0f / (1.0f + __expf(-x));
}
static __device__ __forceinline__ float fast_tanh(float x) {
    return 2.0f / (1.0f + __expf(-2.0f * x)) - 1.0f;
}

__global__ void __launch_bounds__(256) fuse_kernel(
    const float* __restrict__ states,
    const int* __restrict__ cell_mask,
    const float* __restrict__ v,
    float* __restrict__ out)
{
    const int rin = threadIdx.x >> 6;
    const int b = blockIdx.x * 4 + rin;
    const int t = threadIdx.x & 63;
    const int u0 = t * 4;

    const __half* mxp = g_mx + (size_t)b * NX;
    const float4 xz = ld4h(mxp + u0);
    const float4 xr = ld4h(mxp + U_N + u0);
    const float4 xh = ld4h(mxp + 2 * U_N + u0);

    bool m[R_N];
#pragma unroll
    for (int r = 0; r < R_N; r++) m[r] = cell_mask[b * R_N + r] != 0;

    float4 rz[R_N];
    float4 acc = make_float4(0.f, 0.f, 0.f, 0.f);
#pragma unroll
    for (int r = 0; r < R_N; r++) {
        const __half* ip = g_inner + (size_t)b * (R_N * NX) + (size_t)r * NX;
        rz[r] = ld4h(ip + u0);
        const float4 rr  = ld4h(ip + U_N + u0);
        const float4 rhc = ld4h(ip + 2 * U_N + u0);
        if (m[r]) {
            acc.x += rhc.x * fast_sigmoid(xr.x + rr.x);
            acc.y += rhc.y * fast_sigmoid(xr.y + rr.y);
            acc.z += rhc.z * fast_sigmoid(xr.z + rr.z);
            acc.w += rhc.w * fast_sigmoid(xr.w + rr.w);
        }
    }
    float4 hh;
    hh.x = fast_tanh(xh.x + acc.x * 0.25f);
    hh.y = fast_tanh(xh.y + acc.y * 0.25f);
    hh.z = fast_tanh(xh.z + acc.z * 0.25f);
    hh.w = fast_tanh(xh.w + acc.w * 0.25f);

    const float4 vv = ld4(v + u0);
    float part[R_N + 1];
#pragma unroll
    for (int r = 0; r < R_N; r++) {
        part[r] = fast_tanh(xz.x + rz[r].x) * vv.x + fast_tanh(xz.y + rz[r].y) * vv.y
                + fast_tanh(xz.z + rz[r].z) * vv.z + fast_tanh(xz.w + rz[r].w) * vv.w;
    }
    part[R_N] = fast_tanh(xz.x + hh.x) * vv.x + fast_tanh(xz.y + hh.y) * vv.y
              + fast_tanh(xz.z + hh.z) * vv.z + fast_tanh(xz.w + hh.w) * vv.w;

    __shared__ float wsum[8][R_N + 1];
    const int warp = threadIdx.x >> 5;
    const int lane = threadIdx.x & 31;
#pragma unroll
    for (int k = 0; k < R_N + 1; k++) {
        float s = part[k];
#pragma unroll
        for (int off = 16; off > 0; off >>= 1)
            s += __shfl_down_sync(0xffffffffu, s, off);
        if (lane == 0) wsum[warp][k] = s;
    }
    __shared__ float prob_s[4][R_N + 1];
    __syncthreads();
    if (t == 0) {
        float logit[R_N + 1];
        float mx = -INFINITY;
#pragma unroll
        for (int k = 0; k < R_N + 1; k++) {
            float s = wsum[rin * 2][k] + wsum[rin * 2 + 1][k];
            const bool ok = (k == R_N) ? true : m[k];
            logit[k] = ok ? s : -INFINITY;
            mx = fmaxf(mx, logit[k]);
        }
        float denom = 0.f;
        float e[R_N + 1];
#pragma unroll
        for (int k = 0; k < R_N + 1; k++) {
            e[k] = (logit[k] == -INFINITY) ? 0.f : __expf(logit[k] - mx);
            denom += e[k];
        }
#pragma unroll
        for (int k = 0; k < R_N + 1; k++) prob_s[rin][k] = e[k] / denom;
    }
    __syncthreads();

    float4 h = make_float4(0.f, 0.f, 0.f, 0.f);
#pragma unroll
    for (int r = 0; r < R_N; r++) {
        const float4 st = ld4(states + (size_t)b * (R_N * U_N) + r * U_N + u0);
        const float p = prob_s[rin][r];
        h.x += st.x * p; h.y += st.y * p; h.z += st.z * p; h.w += st.w * p;
    }
    const float p4 = prob_s[rin][R_N];
    h.x += hh.x * p4; h.y += hh.y * p4; h.z += hh.z * p4; h.w += hh.w * p4;
    *(float4*)(out + (size_t)b * U_N + u0) = h;
}

extern "C" void kernel_launch(void* const* d_in, const int* in_sizes, int n_in,
                              void* d_out, int out_size) {
    const float* inputs    = (const float*)d_in[0];
    const float* states    = (const float*)d_in[1];
    /* d_in[2] = edge_types (dead in reference) */
    const int*   cell_mask = (const int*)d_in[3];
    const float* kernelW   = (const float*)d_in[4];
    const float* rkernel   = (const float*)d_in[5];
    const float* bias      = (const float*)d_in[6];
    const float* v         = (const float*)d_in[7];
    /* d_in[8] = edge_emb (dead in reference) */
    float* out = (float*)d_out;
    (void)in_sizes; (void)n_in; (void)out_size;

    cudaFuncSetAttribute(gemm_tc, cudaFuncAttributeMaxDynamicSharedMemorySize, DSMEM_BYTES);

    prep_W<<<480, 256>>>(kernelW, rkernel);
    gemm_tc<<<dim3(NT_N, MG_N, NZ), 256, DSMEM_BYTES>>>(
        inputs, states, kernelW, rkernel, bias);
    fuse_kernel<<<B_ROWS / 4, 256>>>(states, cell_mask, v, out);
}

// round 16
// speedup vs baseline: 1.1687x; 1.1464x over previous
#include <cuda_runtime.h>
#include <cuda_bf16.h>
#include <cuda_fp16.h>
#include <cstdint>
#include <math.h>

#define B_ROWS 32768
#define R_N 4
#define U_N 256
#define D_N 256
#define NX 768  /* 3*U */
#define NZ 5
#define MT_N 256   /* M tiles: 32768/128 */
#define NTP_N 3    /* N-tile PAIRS: 6/2 */
#define NT_N 6
#define KC_N 4     /* K chunks: 256/64 */

#if defined(__CUDA_ARCH__) && (defined(__CUDA_ARCH_FEAT_SM103_ALL) || \
    defined(__CUDA_ARCH_FEAT_SM100_ALL) || defined(__CUDA_ARCH_SPECIFIC__))
#define HAS_TCGEN05 1
#else
#define HAS_TCGEN05 0
#endif

// ---------------- global scratch (fp16 intermediates) ----------------
__device__ __half g_mx[(size_t)B_ROWS * NX];
__device__ __half g_inner[(size_t)B_ROWS * R_N * NX];

// Pre-swizzled bf16 W tiles, [z][nt][kc], tile = 128 rows x 128B SW128 = 1024 uint4
__device__ uint4 gW_hi[(size_t)NZ * NT_N * KC_N * 1024];
__device__ uint4 gW_lo[(size_t)NZ * NT_N * KC_N * 1024];

// ---------------- PTX helpers ----------------
static __device__ __forceinline__ uint32_t smem_u32(const void* p) {
    uint32_t a;
    asm("{ .reg .u64 t; cvta.to.shared.u64 t, %1; cvt.u32.u64 %0, t; }" : "=r"(a) : "l"(p));
    return a;
}
static __device__ __forceinline__ uint32_t elect1() {
    uint32_t p;
    asm volatile("{\n\t.reg .pred p;\n\telect.sync _|p, 0xFFFFFFFF;\n\tselp.b32 %0, 1, 0, p;\n\t}" : "=r"(p));
    return p;
}
#define SMEM_DESC_BASE ((2ull<<61)|(1ull<<46)|(64ull<<32)|(1ull<<16))
static __device__ __forceinline__ uint64_t make_desc(uint32_t addr) {
    return SMEM_DESC_BASE | ((uint64_t)(addr >> 4) & 0x3FFFull);
}
#define IDESC_BF16 ((1u<<4)|(1u<<7)|(1u<<10)|((128u/8u)<<17)|((128u/16u)<<24))

#define MBAR_INIT(addr, cnt) \
    asm volatile("mbarrier.init.shared.b64 [%0], %1;" :: "r"(addr), "r"(cnt) : "memory")
#define MBAR_INVAL(addr) \
    asm volatile("mbarrier.inval.shared.b64 [%0];" :: "r"(addr) : "memory")
#define MBAR_WAIT(addr, parity) do {                                              \
    uint32_t _m = (addr), _p = (parity), _d;                                      \
    asm volatile("{\n\t.reg .pred p;\n\t"                                         \
        "mbarrier.try_wait.parity.acquire.cta.shared::cta.b64 p, [%1], %2;\n\t"   \
        "selp.b32 %0, 1, 0, p;\n\t}" : "=r"(_d) : "r"(_m), "r"(_p) : "memory");   \
    if (!_d) {                                                                    \
        asm volatile("{\n\t.reg .pred P1;\n\t"                                    \
            "WL_%=:\n\t"                                                          \
            "mbarrier.try_wait.parity.acquire.cta.shared::cta.b64 P1, [%0], %1, 0x989680;\n\t" \
            "@P1 bra.uni WD_%=;\n\t"                                              \
            "bra.uni WL_%=;\n\t"                                                  \
            "WD_%=:\n\t}" :: "r"(_m), "r"(_p) : "memory");                        \
    } } while (0)

#if HAS_TCGEN05
static __device__ __forceinline__ void mma_f16_ss(uint32_t d_tmem, uint64_t a_desc,
                                                  uint64_t b_desc, uint32_t en) {
    asm volatile(
        "{\n\t"
        ".reg .pred p;\n\t"
        "setp.ne.u32 p, %4, 0;\n\t"
        "tcgen05.mma.cta_group::1.kind::f16 [%0], %1, %2, %3, {%5, %5, %5, %5}, p;\n\t"
        "}"
        :: "r"(d_tmem), "l"(a_desc), "l"(b_desc), "r"(IDESC_BF16), "r"(en), "r"(0u)
        : "memory");
}
#define TC_LD_X32(r, addr)                                                        \
    asm volatile("tcgen05.ld.sync.aligned.32x32b.x32.b32 "                        \
        "{%0, %1, %2, %3, %4, %5, %6, %7, "                                       \
        " %8, %9, %10, %11, %12, %13, %14, %15, "                                 \
        " %16, %17, %18, %19, %20, %21, %22, %23, "                               \
        " %24, %25, %26, %27, %28, %29, %30, %31}, [%32];"                        \
        : "=r"((r)[0]),  "=r"((r)[1]),  "=r"((r)[2]),  "=r"((r)[3]),              \
          "=r"((r)[4]),  "=r"((r)[5]),  "=r"((r)[6]),  "=r"((r)[7]),              \
          "=r"((r)[8]),  "=r"((r)[9]),  "=r"((r)[10]), "=r"((r)[11]),             \
          "=r"((r)[12]), "=r"((r)[13]), "=r"((r)[14]), "=r"((r)[15]),             \
          "=r"((r)[16]), "=r"((r)[17]), "=r"((r)[18]), "=r"((r)[19]),             \
          "=r"((r)[20]), "=r"((r)[21]), "=r"((r)[22]), "=r"((r)[23]),             \
          "=r"((r)[24]), "=r"((r)[25]), "=r"((r)[26]), "=r"((r)[27]),             \
          "=r"((r)[28]), "=r"((r)[29]), "=r"((r)[30]), "=r"((r)[31])              \
        : "r"(addr))
#endif

// ---------------- prep_W: fp32 -> bf16 hi/lo pre-swizzled W tiles ----------------
__global__ void __launch_bounds__(256) prep_W(const float* __restrict__ kernelW,
                                              const float* __restrict__ rkernel) {
    unsigned i = blockIdx.x * 256u + threadIdx.x;      // < 122880
    unsigned g   = i & 7u;
    unsigned nr  = (i >> 3) & 127u;
    unsigned top = i >> 10;           // (z*6+nt)*4+kc
    unsigned kc  = top & 3u;
    unsigned tz  = top >> 2;
    unsigned z   = tz / 6u;
    unsigned nt  = tz % 6u;
    unsigned ncol = nt * 128u + nr;
    unsigned hs[8], ls[8];
#pragma unroll
    for (int j = 0; j < 8; j++) {
        unsigned k = kc * 64u + g * 8u + j;
        float x = (z == 0) ? kernelW[(size_t)k * NX + ncol]
                           : rkernel[((size_t)(z - 1) * U_N + k) * NX + ncol];
        __nv_bfloat16 h = __float2bfloat16_rn(x);
        hs[j] = (unsigned)__bfloat16_as_ushort(h);
        float hf = __bfloat162float(h);
        ls[j] = (unsigned)__bfloat16_as_ushort(__float2bfloat16_rn(x - hf));
    }
    uint4 uh, ul;
    uh.x = hs[0] | (hs[1] << 16); uh.y = hs[2] | (hs[3] << 16);
    uh.z = hs[4] | (hs[5] << 16); uh.w = hs[6] | (hs[7] << 16);
    ul.x = ls[0] | (ls[1] << 16); ul.y = ls[2] | (ls[3] << 16);
    ul.z = ls[4] | (ls[5] << 16); ul.w = ls[6] | (ls[7] << 16);
    unsigned byte = (nr * 8u + g) * 16u;
    unsigned sw = byte ^ ((byte >> 3) & 0x70u);
    gW_hi[(size_t)top * 1024 + (sw >> 4)] = uh;
    gW_lo[(size_t)top * 1024 + (sw >> 4)] = ul;
}

static __device__ __forceinline__ uint2 pack_half4(float4 f) {
    __half2 a = __floats2half2_rn(f.x, f.y);
    __half2 b = __floats2half2_rn(f.z, f.w);
    uint2 o;
    o.x = *(uint32_t*)&a;
    o.y = *(uint32_t*)&b;
    return o;
}

// ---------------- tcgen05 GEMM: 2 N-tiles per CTA share the A tile ----------------
// SMEM from tb (1024-aligned): A hi/lo 32K | W0 hi/lo 32K | W1 hi/lo 32K = 96K
// Epilogue staging (64KB) reuses tb+0.
#define SM_A  0
#define SM_W0 32768
#define SM_W1 65536
#define DSMEM_BYTES 99328

__global__ void __launch_bounds__(256) gemm_tc(
    const float* __restrict__ inputs,
    const float* __restrict__ states,
    const float* __restrict__ kernelW,
    const float* __restrict__ rkernel,
    const float* __restrict__ bias)
{
    extern __shared__ __align__(16) char smem[];
    const uint32_t sb = smem_u32(smem);
    const int tid = threadIdx.x, wid = tid >> 5, lane = tid & 31;
    const int ntp = blockIdx.x, mt = blockIdx.y, z = blockIdx.z;
    const int nt0 = ntp * 2;

    const uint32_t tb = (sb + 1024u + 1023u) & ~1023u;
    char* tbp = smem + (tb - sb);

    const int lda = (z == 0) ? D_N : (R_N * U_N);
    const float* Abase = (z == 0) ? inputs : (states + (z - 1) * U_N);

#if HAS_TCGEN05
    if (wid == 0) {
        asm volatile("tcgen05.alloc.cta_group::1.sync.aligned.shared::cta.b32 [%0], %1;"
                     :: "r"(sb), "r"(256u) : "memory");
        asm volatile("tcgen05.relinquish_alloc_permit.cta_group::1.sync.aligned;");
    }
    if (tid == 0) MBAR_INIT(sb + 8, 1u);
    __syncthreads();
    uint32_t tmem;
    asm volatile("ld.shared.b32 %0, [%1];" : "=r"(tmem) : "r"(sb));

    const unsigned g8 = (unsigned)(tid & 7);     // 16B-group within 64-float row
    const unsigned arw = (unsigned)(tid >> 3);   // row base, 32 rows per pass

    for (int kc = 0; kc < KC_N; kc++) {
        // Full-drain lag-1 protocol (proven R4/R7/R12/R13): exact.
        if (kc > 0) MBAR_WAIT(sb + 8, (unsigned)((kc - 1) & 1));
        // ---- A (single tile, shared by both nt): fp32 -> bf16 hi/lo, SW128 ----
        {
            uint4* sAh = (uint4*)(tbp + SM_A);
            uint4* sAl = (uint4*)(tbp + SM_A + 16384);
            const float* srcb = Abase + (size_t)(mt * 128) * lda + kc * 64 + g8 * 8;
#pragma unroll
            for (int j = 0; j < 4; j++) {
                unsigned row = arw + j * 32;
                const float* src = srcb + (size_t)row * lda;
                float4 f0 = *(const float4*)src;
                float4 f1 = *(const float4*)(src + 4);
                float x[8] = {f0.x, f0.y, f0.z, f0.w, f1.x, f1.y, f1.z, f1.w};
                unsigned hs[8], lsv[8];
#pragma unroll
                for (int e = 0; e < 8; e++) {
                    __nv_bfloat16 h = __float2bfloat16_rn(x[e]);
                    hs[e] = (unsigned)__bfloat16_as_ushort(h);
                    lsv[e] = (unsigned)__bfloat16_as_ushort(
                        __float2bfloat16_rn(x[e] - __bfloat162float(h)));
                }
                uint4 uh, ul;
                uh.x = hs[0] | (hs[1] << 16); uh.y = hs[2] | (hs[3] << 16);
                uh.z = hs[4] | (hs[5] << 16); uh.w = hs[6] | (hs[7] << 16);
                ul.x = lsv[0] | (lsv[1] << 16); ul.y = lsv[2] | (lsv[3] << 16);
                ul.z = lsv[4] | (lsv[5] << 16); ul.w = lsv[6] | (lsv[7] << 16);
                unsigned byte = row * 128u + g8 * 16u;
                unsigned sw = byte ^ ((byte >> 3) & 0x70u);
                sAh[sw >> 4] = uh;
                sAl[sw >> 4] = ul;
            }
        }
        // ---- W for both nt tiles: identity uint4 copies of pre-swizzled tiles ----
#pragma unroll
        for (int t = 0; t < 2; t++) {
            const size_t tB = ((size_t)((z * NT_N + nt0 + t) * KC_N + kc)) * 1024;
            uint4* sWh = (uint4*)(tbp + (t ? SM_W1 : SM_W0));
            uint4* sWl = (uint4*)(tbp + (t ? SM_W1 : SM_W0) + 16384);
#pragma unroll
            for (int j = 0; j < 4; j++) {
                int idx = tid + j * 256;
                sWh[idx] = gW_hi[tB + idx];
                sWl[idx] = gW_lo[tB + idx];
            }
        }
        asm volatile("fence.proxy.async.shared::cta;" ::: "memory");
        __syncthreads();
        if (wid == 0 && elect1()) {
            const uint64_t dAh = make_desc(tb + SM_A);
            const uint64_t dAl = make_desc(tb + SM_A + 16384);
#pragma unroll
            for (int t = 0; t < 2; t++) {
                const uint32_t dz = tmem + (unsigned)(t * 128);
                const uint64_t dBh = make_desc(tb + (t ? SM_W1 : SM_W0));
                const uint64_t dBl = make_desc(tb + (t ? SM_W1 : SM_W0) + 16384);
#pragma unroll
                for (int ks = 0; ks < 4; ks++) {
                    uint64_t off = (uint64_t)(ks * 2);
                    mma_f16_ss(dz, dAh + off, dBh + off, (kc == 0 && ks == 0) ? 0u : 1u);
                    mma_f16_ss(dz, dAh + off, dBl + off, 1u);
                    mma_f16_ss(dz, dAl + off, dBh + off, 1u);
                }
            }
            asm volatile(
                "tcgen05.commit.cta_group::1.mbarrier::arrive::one.shared::cluster.b64 [%0];"
                :: "r"(sb + 8) : "memory");
        }
    }
    MBAR_WAIT(sb + 8, 1u);   // 4 commits -> exact (c=4)
    asm volatile("tcgen05.fence::after_thread_sync;" ::: "memory");

    // ---- epilogue per nt tile: TMEM -> swizzled stage -> coalesced fp16 global ----
    const int cb = (wid >> 2) * 64;
    const int row = (wid & 3) * 32 + lane;
#pragma unroll 1
    for (int t = 0; t < 2; t++) {
        const uint32_t dcol = (unsigned)(t * 128);
        const int n0 = (nt0 + t) * 128;
#pragma unroll
        for (int half = 0; half < 2; half++) {
            uint32_t r[32];
            TC_LD_X32(r, tmem + dcol + (uint32_t)(cb + half * 32));
            asm volatile("tcgen05.wait::ld.sync.aligned;" ::: "memory");
#pragma unroll
            for (int q = 0; q < 8; q++) {
                int col = cb + half * 32 + q * 4;
                unsigned byte = (unsigned)row * 512u + (unsigned)col * 4u;
                unsigned phys = byte ^ (((unsigned)row & 7u) << 4);
                *(uint4*)(tbp + phys) = make_uint4(r[q*4+0], r[q*4+1], r[q*4+2], r[q*4+3]);
            }
        }
        __syncthreads();
#pragma unroll
        for (int it = 0; it < 16; it++) {
            int i2 = tid + it * 256;
            int rw = i2 >> 5, c4 = i2 & 31;
            unsigned byte = (unsigned)rw * 512u + (unsigned)c4 * 16u;
            unsigned phys = byte ^ (((unsigned)rw & 7u) << 4);
            uint4 v = *(const uint4*)(tbp + phys);
            float4 f;
            f.x = __uint_as_float(v.x); f.y = __uint_as_float(v.y);
            f.z = __uint_as_float(v.z); f.w = __uint_as_float(v.w);
            const float4 b4 = *(const float4*)(bias + (size_t)z * NX + n0 + c4 * 4);
            f.x += b4.x; f.y += b4.y; f.z += b4.z; f.w += b4.w;
            size_t rg = (size_t)mt * 128 + rw;
            __half* dst = (z == 0)
                ? (g_mx + rg * NX + n0 + c4 * 4)
                : (g_inner + rg * (R_N * NX) + (size_t)(z - 1) * NX + n0 + c4 * 4);
            *(uint2*)dst = pack_half4(f);
        }
        __syncthreads();
    }
    if (tid == 0) MBAR_INVAL(sb + 8);
    __syncthreads();
    if (wid == 0) {
        asm volatile("tcgen05.dealloc.cta_group::1.sync.aligned.b32 %0, %1;"
                     :: "r"(tmem), "r"(256u));
    }
#else
    // fp32 fallback (generic PTX pass only; never executed with sm_103a cubin)
    __syncthreads();
    for (int t = 0; t < 2; t++) {
        const int nt = nt0 + t;
        const int frow = tid >> 1;
        const int fc0 = (tid & 1) * 64;
        float facc[64];
        for (int j = 0; j < 64; j++) facc[j] = 0.f;
        for (int k = 0; k < D_N; k++) {
            float a = Abase[(size_t)(mt * 128 + frow) * lda + k];
            for (int j = 0; j < 64; j++) {
                int ncol = nt * 128 + fc0 + j;
                float wv = (z == 0) ? kernelW[(size_t)k * NX + ncol]
                                    : rkernel[((size_t)(z - 1) * U_N + k) * NX + ncol];
                facc[j] = fmaf(a, wv, facc[j]);
            }
        }
        size_t rg = (size_t)mt * 128 + frow;
        const int n0f = nt * 128;
        for (int j = 0; j < 64; j++) {
            float f = facc[j] + bias[(size_t)z * NX + n0f + fc0 + j];
            __half* dst = (z == 0)
                ? (g_mx + rg * NX + n0f + fc0 + j)
                : (g_inner + rg * (R_N * NX) + (size_t)(z - 1) * NX + n0f + fc0 + j);
            *dst = __float2half_rn(f);
        }
    }
#endif
}

// ---------------- vectorized fused epilogue (unchanged from R13 pass) ----------------
static __device__ __forceinline__ float4 ld4(const float* p) { return *(const float4*)p; }
static __device__ __forceinline__ float4 ld4h(const __half* p) {
    uint2 u = *(const uint2*)p;
    __half2 a = *(__half2*)&u.x;
    __half2 b = *(__half2*)&u.y;
    float4 f;
    f.x = __low2float(a); f.y = __high2float(a);
    f.z = __low2float(b); f.w = __high2float(b);
    return f;
}
static __device__ __forceinline__ float fast_sigmoid(float x) {
    return 1.0f / (1.0f + __expf(-x));
}
static __device__ __forceinline__ float fast_tanh(float x) {
    return 2.0f / (1.0f + __expf(-2.0f * x)) - 1.0f;
}

__global__ void __launch_bounds__(256) fuse_kernel(
    const float* __restrict__ states,
    const int* __restrict__ cell_mask,
    const float* __restrict__ v,
    float* __restrict__ out)
{
    const int rin = threadIdx.x >> 6;
    const int b = blockIdx.x * 4 + rin;
    const int t = threadIdx.x & 63;
    const int u0 = t * 4;

    const __half* mxp = g_mx + (size_t)b * NX;
    const float4 xz = ld4h(mxp + u0);
    const float4 xr = ld4h(mxp + U_N + u0);
    const float4 xh = ld4h(mxp + 2 * U_N + u0);

    bool m[R_N];
#pragma unroll
    for (int r = 0; r < R_N; r++) m[r] = cell_mask[b * R_N + r] != 0;

    float4 rz[R_N];
    float4 acc = make_float4(0.f, 0.f, 0.f, 0.f);
#pragma unroll
    for (int r = 0; r < R_N; r++) {
        const __half* ip = g_inner + (size_t)b * (R_N * NX) + (size_t)r * NX;
        rz[r] = ld4h(ip + u0);
        const float4 rr  = ld4h(ip + U_N + u0);
        const float4 rhc = ld4h(ip + 2 * U_N + u0);
        if (m[r]) {
            acc.x += rhc.x * fast_sigmoid(xr.x + rr.x);
            acc.y += rhc.y * fast_sigmoid(xr.y + rr.y);
            acc.z += rhc.z * fast_sigmoid(xr.z + rr.z);
            acc.w += rhc.w * fast_sigmoid(xr.w + rr.w);
        }
    }
    float4 hh;
    hh.x = fast_tanh(xh.x + acc.x * 0.25f);
    hh.y = fast_tanh(xh.y + acc.y * 0.25f);
    hh.z = fast_tanh(xh.z + acc.z * 0.25f);
    hh.w = fast_tanh(xh.w + acc.w * 0.25f);

    const float4 vv = ld4(v + u0);
    float part[R_N + 1];
#pragma unroll
    for (int r = 0; r < R_N; r++) {
        part[r] = fast_tanh(xz.x + rz[r].x) * vv.x + fast_tanh(xz.y + rz[r].y) * vv.y
                + fast_tanh(xz.z + rz[r].z) * vv.z + fast_tanh(xz.w + rz[r].w) * vv.w;
    }
    part[R_N] = fast_tanh(xz.x + hh.x) * vv.x + fast_tanh(xz.y + hh.y) * vv.y
              + fast_tanh(xz.z + hh.z) * vv.z + fast_tanh(xz.w + hh.w) * vv.w;

    __shared__ float wsum[8][R_N + 1];
    const int warp = threadIdx.x >> 5;
    const int lane = threadIdx.x & 31;
#pragma unroll
    for (int k = 0; k < R_N + 1; k++) {
        float s = part[k];
#pragma unroll
        for (int off = 16; off > 0; off >>= 1)
            s += __shfl_down_sync(0xffffffffu, s, off);
        if (lane == 0) wsum[warp][k] = s;
    }
    __shared__ float prob_s[4][R_N + 1];
    __syncthreads();
    if (t == 0) {
        float logit[R_N + 1];
        float mx = -INFINITY;
#pragma unroll
        for (int k = 0; k < R_N + 1; k++) {
            float s = wsum[rin * 2][k] + wsum[rin * 2 + 1][k];
            const bool ok = (k == R_N) ? true : m[k];
            logit[k] = ok ? s : -INFINITY;
            mx = fmaxf(mx, logit[k]);
        }
        float denom = 0.f;
        float e[R_N + 1];
#pragma unroll
        for (int k = 0; k < R_N + 1; k++) {
            e[k] = (logit[k] == -INFINITY) ? 0.f : __expf(logit[k] - mx);
            denom += e[k];
        }
#pragma unroll
        for (int k = 0; k < R_N + 1; k++) prob_s[rin][k] = e[k] / denom;
    }
    __syncthreads();

    float4 h = make_float4(0.f, 0.f, 0.f, 0.f);
#pragma unroll
    for (int r = 0; r < R_N; r++) {
        const float4 st = ld4(states + (size_t)b * (R_N * U_N) + r * U_N + u0);
        const float p = prob_s[rin][r];
        h.x += st.x * p; h.y += st.y * p; h.z += st.z * p; h.w += st.w * p;
    }
    const float p4 = prob_s[rin][R_N];
    h.x += hh.x * p4; h.y += hh.y * p4; h.z += hh.z * p4; h.w += hh.w * p4;
    *(float4*)(out + (size_t)b * U_N + u0) = h;
}

extern "C" void kernel_launch(void* const* d_in, const int* in_sizes, int n_in,
                              void* d_out, int out_size) {
    const float* inputs    = (const float*)d_in[0];
    const float* states    = (const float*)d_in[1];
    /* d_in[2] = edge_types (dead in reference) */
    const int*   cell_mask = (const int*)d_in[3];
    const float* kernelW   = (const float*)d_in[4];
    const float* rkernel   = (const float*)d_in[5];
    const float* bias      = (const float*)d_in[6];
    const float* v         = (const float*)d_in[7];
    /* d_in[8] = edge_emb (dead in reference) */
    float* out = (float*)d_out;
    (void)in_sizes; (void)n_in; (void)out_size;

    cudaFuncSetAttribute(gemm_tc, cudaFuncAttributeMaxDynamicSharedMemorySize, DSMEM_BYTES);

    prep_W<<<480, 256>>>(kernelW, rkernel);
    gemm_tc<<<dim3(NTP_N, MT_N, NZ), 256, DSMEM_BYTES>>>(
        inputs, states, kernelW, rkernel, bias);
    fuse_kernel<<<B_ROWS / 4, 256>>>(states, cell_mask, v, out);
}

// round 17
// speedup vs baseline: 1.3540x; 1.1586x over previous
#include <cuda_runtime.h>
#include <cuda_bf16.h>
#include <cuda_fp16.h>
#include <cstdint>
#include <math.h>

#define B_ROWS 32768
#define R_N 4
#define U_N 256
#define D_N 256
#define NX 768  /* 3*U */
#define NZ 5
#define MT_N 256   /* M tiles: 32768/128 */
#define NTP_N 3    /* N-tile PAIRS: 6/2 */
#define NT_N 6
#define KC_N 4     /* K chunks: 256/64 */

#if defined(__CUDA_ARCH__) && (defined(__CUDA_ARCH_FEAT_SM103_ALL) || \
    defined(__CUDA_ARCH_FEAT_SM100_ALL) || defined(__CUDA_ARCH_SPECIFIC__))
#define HAS_TCGEN05 1
#else
#define HAS_TCGEN05 0
#endif

// ---------------- global scratch (fp16 intermediates) ----------------
__device__ __half g_mx[(size_t)B_ROWS * NX];
__device__ __half g_inner[(size_t)B_ROWS * R_N * NX];

// Pre-swizzled fp16 W tiles (single precision level), [z][nt][kc],
// tile = 128 rows x 128B SW128 = 1024 uint4
__device__ uint4 gW16[(size_t)NZ * NT_N * KC_N * 1024];

// ---------------- PTX helpers ----------------
static __device__ __forceinline__ uint32_t smem_u32(const void* p) {
    uint32_t a;
    asm("{ .reg .u64 t; cvta.to.shared.u64 t, %1; cvt.u32.u64 %0, t; }" : "=r"(a) : "l"(p));
    return a;
}
static __device__ __forceinline__ uint32_t elect1() {
    uint32_t p;
    asm volatile("{\n\t.reg .pred p;\n\telect.sync _|p, 0xFFFFFFFF;\n\tselp.b32 %0, 1, 0, p;\n\t}" : "=r"(p));
    return p;
}
#define SMEM_DESC_BASE ((2ull<<61)|(1ull<<46)|(64ull<<32)|(1ull<<16))
static __device__ __forceinline__ uint64_t make_desc(uint32_t addr) {
    return SMEM_DESC_BASE | ((uint64_t)(addr >> 4) & 0x3FFFull);
}
// idesc: dtype F32 (1<<4), atype F16 (0<<7), btype F16 (0<<10), N=128, M=128
#define IDESC_F16 ((1u<<4)|((128u/8u)<<17)|((128u/16u)<<24))

#define MBAR_INIT(addr, cnt) \
    asm volatile("mbarrier.init.shared.b64 [%0], %1;" :: "r"(addr), "r"(cnt) : "memory")
#define MBAR_INVAL(addr) \
    asm volatile("mbarrier.inval.shared.b64 [%0];" :: "r"(addr) : "memory")
#define MBAR_WAIT(addr, parity) do {                                              \
    uint32_t _m = (addr), _p = (parity), _d;                                      \
    asm volatile("{\n\t.reg .pred p;\n\t"                                         \
        "mbarrier.try_wait.parity.acquire.cta.shared::cta.b64 p, [%1], %2;\n\t"   \
        "selp.b32 %0, 1, 0, p;\n\t}" : "=r"(_d) : "r"(_m), "r"(_p) : "memory");   \
    if (!_d) {                                                                    \
        asm volatile("{\n\t.reg .pred P1;\n\t"                                    \
            "WL_%=:\n\t"                                                          \
            "mbarrier.try_wait.parity.acquire.cta.shared::cta.b64 P1, [%0], %1, 0x989680;\n\t" \
            "@P1 bra.uni WD_%=;\n\t"                                              \
            "bra.uni WL_%=;\n\t"                                                  \
            "WD_%=:\n\t}" :: "r"(_m), "r"(_p) : "memory");                        \
    } } while (0)

#if HAS_TCGEN05
static __device__ __forceinline__ void mma_f16_ss(uint32_t d_tmem, uint64_t a_desc,
                                                  uint64_t b_desc, uint32_t en) {
    asm volatile(
        "{\n\t"
        ".reg .pred p;\n\t"
        "setp.ne.u32 p, %4, 0;\n\t"
        "tcgen05.mma.cta_group::1.kind::f16 [%0], %1, %2, %3, {%5, %5, %5, %5}, p;\n\t"
        "}"
        :: "r"(d_tmem), "l"(a_desc), "l"(b_desc), "r"(IDESC_F16), "r"(en), "r"(0u)
        : "memory");
}
#define TC_LD_X32(r, addr)                                                        \
    asm volatile("tcgen05.ld.sync.aligned.32x32b.x32.b32 "                        \
        "{%0, %1, %2, %3, %4, %5, %6, %7, "                                       \
        " %8, %9, %10, %11, %12, %13, %14, %15, "                                 \
        " %16, %17, %18, %19, %20, %21, %22, %23, "                               \
        " %24, %25, %26, %27, %28, %29, %30, %31}, [%32];"                        \
        : "=r"((r)[0]),  "=r"((r)[1]),  "=r"((r)[2]),  "=r"((r)[3]),              \
          "=r"((r)[4]),  "=r"((r)[5]),  "=r"((r)[6]),  "=r"((r)[7]),              \
          "=r"((r)[8]),  "=r"((r)[9]),  "=r"((r)[10]), "=r"((r)[11]),             \
          "=r"((r)[12]), "=r"((r)[13]), "=r"((r)[14]), "=r"((r)[15]),             \
          "=r"((r)[16]), "=r"((r)[17]), "=r"((r)[18]), "=r"((r)[19]),             \
          "=r"((r)[20]), "=r"((r)[21]), "=r"((r)[22]), "=r"((r)[23]),             \
          "=r"((r)[24]), "=r"((r)[25]), "=r"((r)[26]), "=r"((r)[27]),             \
          "=r"((r)[28]), "=r"((r)[29]), "=r"((r)[30]), "=r"((r)[31])              \
        : "r"(addr))
#endif

// ---------------- prep_W: fp32 -> single fp16 pre-swizzled W tiles ----------------
__global__ void __launch_bounds__(256) prep_W(const float* __restrict__ kernelW,
                                              const float* __restrict__ rkernel) {
    unsigned i = blockIdx.x * 256u + threadIdx.x;      // < 122880
    unsigned g   = i & 7u;
    unsigned nr  = (i >> 3) & 127u;
    unsigned top = i >> 10;           // (z*6+nt)*4+kc
    unsigned kc  = top & 3u;
    unsigned tz  = top >> 2;
    unsigned z   = tz / 6u;
    unsigned nt  = tz % 6u;
    unsigned ncol = nt * 128u + nr;
    unsigned hs[8];
#pragma unroll
    for (int j = 0; j < 8; j++) {
        unsigned k = kc * 64u + g * 8u + j;
        float x = (z == 0) ? kernelW[(size_t)k * NX + ncol]
                           : rkernel[((size_t)(z - 1) * U_N + k) * NX + ncol];
        hs[j] = (unsigned)__half_as_ushort(__float2half_rn(x));
    }
    uint4 uh;
    uh.x = hs[0] | (hs[1] << 16); uh.y = hs[2] | (hs[3] << 16);
    uh.z = hs[4] | (hs[5] << 16); uh.w = hs[6] | (hs[7] << 16);
    unsigned byte = (nr * 8u + g) * 16u;
    unsigned sw = byte ^ ((byte >> 3) & 0x70u);
    gW16[(size_t)top * 1024 + (sw >> 4)] = uh;
}

static __device__ __forceinline__ uint2 pack_half4(float4 f) {
    __half2 a = __floats2half2_rn(f.x, f.y);
    __half2 b = __floats2half2_rn(f.z, f.w);
    uint2 o;
    o.x = *(uint32_t*)&a;
    o.y = *(uint32_t*)&b;
    return o;
}

// ---------------- tcgen05 GEMM: 2 N-tiles share A; A fp16 hi/lo, W fp16, 2 passes ----------------
// SMEM from tb (1024-aligned): A hi 16K | A lo 16K | W0 16K | W1 16K = 64K
// Epilogue staging needs 64KB and reuses tb+0..65536.
#define SM_AH 0
#define SM_AL 16384
#define SM_W0 32768
#define SM_W1 49152
#define DSMEM_BYTES 67584

__global__ void __launch_bounds__(256) gemm_tc(
    const float* __restrict__ inputs,
    const float* __restrict__ states,
    const float* __restrict__ kernelW,
    const float* __restrict__ rkernel,
    const float* __restrict__ bias)
{
    extern __shared__ __align__(16) char smem[];
    const uint32_t sb = smem_u32(smem);
    const int tid = threadIdx.x, wid = tid >> 5, lane = tid & 31;
    const int ntp = blockIdx.x, mt = blockIdx.y, z = blockIdx.z;
    const int nt0 = ntp * 2;

    const uint32_t tb = (sb + 1024u + 1023u) & ~1023u;
    char* tbp = smem + (tb - sb);

    const int lda = (z == 0) ? D_N : (R_N * U_N);
    const float* Abase = (z == 0) ? inputs : (states + (z - 1) * U_N);

#if HAS_TCGEN05
    if (wid == 0) {
        asm volatile("tcgen05.alloc.cta_group::1.sync.aligned.shared::cta.b32 [%0], %1;"
                     :: "r"(sb), "r"(256u) : "memory");
        asm volatile("tcgen05.relinquish_alloc_permit.cta_group::1.sync.aligned;");
    }
    if (tid == 0) MBAR_INIT(sb + 8, 1u);
    __syncthreads();
    uint32_t tmem;
    asm volatile("ld.shared.b32 %0, [%1];" : "=r"(tmem) : "r"(sb));

    const unsigned g8 = (unsigned)(tid & 7);     // 16B-group within 64-float row
    const unsigned arw = (unsigned)(tid >> 3);   // row base, 32 rows per pass

    for (int kc = 0; kc < KC_N; kc++) {
        // Full-drain lag-1 protocol (proven R4/R7/R12/R13/R16): exact.
        if (kc > 0) MBAR_WAIT(sb + 8, (unsigned)((kc - 1) & 1));
        // ---- A (shared): fp32 -> fp16 hi + fp16 residual, SW128 ----
        {
            uint4* sAh = (uint4*)(tbp + SM_AH);
            uint4* sAl = (uint4*)(tbp + SM_AL);
            const float* srcb = Abase + (size_t)(mt * 128) * lda + kc * 64 + g8 * 8;
#pragma unroll
            for (int j = 0; j < 4; j++) {
                unsigned row = arw + j * 32;
                const float* src = srcb + (size_t)row * lda;
                float4 f0 = *(const float4*)src;
                float4 f1 = *(const float4*)(src + 4);
                float x[8] = {f0.x, f0.y, f0.z, f0.w, f1.x, f1.y, f1.z, f1.w};
                unsigned hs[8], lsv[8];
#pragma unroll
                for (int e = 0; e < 8; e++) {
                    __half h = __float2half_rn(x[e]);
                    hs[e] = (unsigned)__half_as_ushort(h);
                    lsv[e] = (unsigned)__half_as_ushort(
                        __float2half_rn(x[e] - __half2float(h)));
                }
                uint4 uh, ul;
                uh.x = hs[0] | (hs[1] << 16); uh.y = hs[2] | (hs[3] << 16);
                uh.z = hs[4] | (hs[5] << 16); uh.w = hs[6] | (hs[7] << 16);
                ul.x = lsv[0] | (lsv[1] << 16); ul.y = lsv[2] | (lsv[3] << 16);
                ul.z = lsv[4] | (lsv[5] << 16); ul.w = lsv[6] | (lsv[7] << 16);
                unsigned byte = row * 128u + g8 * 16u;
                unsigned sw = byte ^ ((byte >> 3) & 0x70u);
                sAh[sw >> 4] = uh;
                sAl[sw >> 4] = ul;
            }
        }
        // ---- W for both nt tiles: identity uint4 copies ----
#pragma unroll
        for (int t = 0; t < 2; t++) {
            const size_t tB = ((size_t)((z * NT_N + nt0 + t) * KC_N + kc)) * 1024;
            uint4* sW = (uint4*)(tbp + (t ? SM_W1 : SM_W0));
#pragma unroll
            for (int j = 0; j < 4; j++) {
                int idx = tid + j * 256;
                sW[idx] = gW16[tB + idx];
            }
        }
        asm volatile("fence.proxy.async.shared::cta;" ::: "memory");
        __syncthreads();
        if (wid == 0 && elect1()) {
            const uint64_t dAh = make_desc(tb + SM_AH);
            const uint64_t dAl = make_desc(tb + SM_AL);
#pragma unroll
            for (int t = 0; t < 2; t++) {
                const uint32_t dz = tmem + (unsigned)(t * 128);
                const uint64_t dW = make_desc(tb + (t ? SM_W1 : SM_W0));
#pragma unroll
                for (int ks = 0; ks < 4; ks++) {
                    uint64_t off = (uint64_t)(ks * 2);
                    mma_f16_ss(dz, dAh + off, dW + off, (kc == 0 && ks == 0) ? 0u : 1u);
                    mma_f16_ss(dz, dAl + off, dW + off, 1u);
                }
            }
            asm volatile(
                "tcgen05.commit.cta_group::1.mbarrier::arrive::one.shared::cluster.b64 [%0];"
                :: "r"(sb + 8) : "memory");
        }
    }
    MBAR_WAIT(sb + 8, 1u);   // 4 commits -> exact (c=4)
    asm volatile("tcgen05.fence::after_thread_sync;" ::: "memory");

    // ---- epilogue per nt tile: TMEM -> swizzled stage -> coalesced fp16 global ----
    const int cb = (wid >> 2) * 64;
    const int row = (wid & 3) * 32 + lane;
#pragma unroll 1
    for (int t = 0; t < 2; t++) {
        const uint32_t dcol = (unsigned)(t * 128);
        const int n0 = (nt0 + t) * 128;
#pragma unroll
        for (int half = 0; half < 2; half++) {
            uint32_t r[32];
            TC_LD_X32(r, tmem + dcol + (uint32_t)(cb + half * 32));
            asm volatile("tcgen05.wait::ld.sync.aligned;" ::: "memory");
#pragma unroll
            for (int q = 0; q < 8; q++) {
                int col = cb + half * 32 + q * 4;
                unsigned byte = (unsigned)row * 512u + (unsigned)col * 4u;
                unsigned phys = byte ^ (((unsigned)row & 7u) << 4);
                *(uint4*)(tbp + phys) = make_uint4(r[q*4+0], r[q*4+1], r[q*4+2], r[q*4+3]);
            }
        }
        __syncthreads();
#pragma unroll
        for (int it = 0; it < 16; it++) {
            int i2 = tid + it * 256;
            int rw = i2 >> 5, c4 = i2 & 31;
            unsigned byte = (unsigned)rw * 512u + (unsigned)c4 * 16u;
            unsigned phys = byte ^ (((unsigned)rw & 7u) << 4);
            uint4 v = *(const uint4*)(tbp + phys);
            float4 f;
            f.x = __uint_as_float(v.x); f.y = __uint_as_float(v.y);
            f.z = __uint_as_float(v.z); f.w = __uint_as_float(v.w);
            const float4 b4 = *(const float4*)(bias + (size_t)z * NX + n0 + c4 * 4);
            f.x += b4.x; f.y += b4.y; f.z += b4.z; f.w += b4.w;
            size_t rg = (size_t)mt * 128 + rw;
            __half* dst = (z == 0)
                ? (g_mx + rg * NX + n0 + c4 * 4)
                : (g_inner + rg * (R_N * NX) + (size_t)(z - 1) * NX + n0 + c4 * 4);
            *(uint2*)dst = pack_half4(f);
        }
        __syncthreads();
    }
    if (tid == 0) MBAR_INVAL(sb + 8);
    __syncthreads();
    if (wid == 0) {
        asm volatile("tcgen05.dealloc.cta_group::1.sync.aligned.b32 %0, %1;"
                     :: "r"(tmem), "r"(256u));
    }
#else
    // fp32 fallback (generic PTX pass only; never executed with sm_103a cubin)
    __syncthreads();
    for (int t = 0; t < 2; t++) {
        const int nt = nt0 + t;
        const int frow = tid >> 1;
        const int fc0 = (tid & 1) * 64;
        float facc[64];
        for (int j = 0; j < 64; j++) facc[j] = 0.f;
        for (int k = 0; k < D_N; k++) {
            float a = Abase[(size_t)(mt * 128 + frow) * lda + k];
            for (int j = 0; j < 64; j++) {
                int ncol = nt * 128 + fc0 + j;
                float wv = (z == 0) ? kernelW[(size_t)k * NX + ncol]
                                    : rkernel[((size_t)(z - 1) * U_N + k) * NX + ncol];
                facc[j] = fmaf(a, wv, facc[j]);
            }
        }
        size_t rg = (size_t)mt * 128 + frow;
        const int n0f = nt * 128;
        for (int j = 0; j < 64; j++) {
            float f = facc[j] + bias[(size_t)z * NX + n0f + fc0 + j];
            __half* dst = (z == 0)
                ? (g_mx + rg * NX + n0f + fc0 + j)
                : (g_inner + rg * (R_N * NX) + (size_t)(z - 1) * NX + n0f + fc0 + j);
            *dst = __float2half_rn(f);
        }
    }
#endif
}

// ---------------- vectorized fused epilogue (unchanged from R13/R16 pass) ----------------
static __device__ __forceinline__ float4 ld4(const float* p) { return *(const float4*)p; }
static __device__ __forceinline__ float4 ld4h(const __half* p) {
    uint2 u = *(const uint2*)p;
    __half2 a = *(__half2*)&u.x;
    __half2 b = *(__half2*)&u.y;
    float4 f;
    f.x = __low2float(a); f.y = __high2float(a);
    f.z = __low2float(b); f.w = __high2float(b);
    return f;
}
static __device__ __forceinline__ float fast_sigmoid(float x) {
    return 1.0f / (1.0f + __expf(-x));
}
static __device__ __forceinline__ float fast_tanh(float x) {
    return 2.0f / (1.0f + __expf(-2.0f * x)) - 1.0f;
}

__global__ void __launch_bounds__(256) fuse_kernel(
    const float* __restrict__ states,
    const int* __restrict__ cell_mask,
    const float* __restrict__ v,
    float* __restrict__ out)
{
    const int rin = threadIdx.x >> 6;
    const int b = blockIdx.x * 4 + rin;
    const int t = threadIdx.x & 63;
    const int u0 = t * 4;

    const __half* mxp = g_mx + (size_t)b * NX;
    const float4 xz = ld4h(mxp + u0);
    const float4 xr = ld4h(mxp + U_N + u0);
    const float4 xh = ld4h(mxp + 2 * U_N + u0);

    bool m[R_N];
#pragma unroll
    for (int r = 0; r < R_N; r++) m[r] = cell_mask[b * R_N + r] != 0;

    float4 rz[R_N];
    float4 acc = make_float4(0.f, 0.f, 0.f, 0.f);
#pragma unroll
    for (int r = 0; r < R_N; r++) {
        const __half* ip = g_inner + (size_t)b * (R_N * NX) + (size_t)r * NX;
        rz[r] = ld4h(ip + u0);
        const float4 rr  = ld4h(ip + U_N + u0);
        const float4 rhc = ld4h(ip + 2 * U_N + u0);
        if (m[r]) {
            acc.x += rhc.x * fast_sigmoid(xr.x + rr.x);
            acc.y += rhc.y * fast_sigmoid(xr.y + rr.y);
            acc.z += rhc.z * fast_sigmoid(xr.z + rr.z);
            acc.w += rhc.w * fast_sigmoid(xr.w + rr.w);
        }
    }
    float4 hh;
    hh.x = fast_tanh(xh.x + acc.x * 0.25f);
    hh.y = fast_tanh(xh.y + acc.y * 0.25f);
    hh.z = fast_tanh(xh.z + acc.z * 0.25f);
    hh.w = fast_tanh(xh.w + acc.w * 0.25f);

    const float4 vv = ld4(v + u0);
    float part[R_N + 1];
#pragma unroll
    for (int r = 0; r < R_N; r++) {
        part[r] = fast_tanh(xz.x + rz[r].x) * vv.x + fast_tanh(xz.y + rz[r].y) * vv.y
                + fast_tanh(xz.z + rz[r].z) * vv.z + fast_tanh(xz.w + rz[r].w) * vv.w;
    }
    part[R_N] = fast_tanh(xz.x + hh.x) * vv.x + fast_tanh(xz.y + hh.y) * vv.y
              + fast_tanh(xz.z + hh.z) * vv.z + fast_tanh(xz.w + hh.w) * vv.w;

    __shared__ float wsum[8][R_N + 1];
    const int warp = threadIdx.x >> 5;
    const int lane = threadIdx.x & 31;
#pragma unroll
    for (int k = 0; k < R_N + 1; k++) {
        float s = part[k];
#pragma unroll
        for (int off = 16; off > 0; off >>= 1)
            s += __shfl_down_sync(0xffffffffu, s, off);
        if (lane == 0) wsum[warp][k] = s;
    }
    __shared__ float prob_s[4][R_N + 1];
    __syncthreads();
    if (t == 0) {
        float logit[R_N + 1];
        float mx = -INFINITY;
#pragma unroll
        for (int k = 0; k < R_N + 1; k++) {
            float s = wsum[rin * 2][k] + wsum[rin * 2 + 1][k];
            const bool ok = (k == R_N) ? true : m[k];
            logit[k] = ok ? s : -INFINITY;
            mx = fmaxf(mx, logit[k]);
        }
        float denom = 0.f;
        float e[R_N + 1];
#pragma unroll
        for (int k = 0; k < R_N + 1; k++) {
            e[k] = (logit[k] == -INFINITY) ? 0.f : __expf(logit[k] - mx);
            denom += e[k];
        }
#pragma unroll
        for (int k = 0; k < R_N + 1; k++) prob_s[rin][k] = e[k] / denom;
    }
    __syncthreads();

    float4 h = make_float4(0.f, 0.f, 0.f, 0.f);
#pragma unroll
    for (int r = 0; r < R_N; r++) {
        const float4 st = ld4(states + (size_t)b * (R_N * U_N) + r * U_N + u0);
        const float p = prob_s[rin][r];
        h.x += st.x * p; h.y += st.y * p; h.z += st.z * p; h.w += st.w * p;
    }
    const float p4 = prob_s[rin][R_N];
    h.x += hh.x * p4; h.y += hh.y * p4; h.z += hh.z * p4; h.w += hh.w * p4;
    *(float4*)(out + (size_t)b * U_N + u0) = h;
}

extern "C" void kernel_launch(void* const* d_in, const int* in_sizes, int n_in,
                              void* d_out, int out_size) {
    const float* inputs    = (const float*)d_in[0];
    const float* states    = (const float*)d_in[1];
    /* d_in[2] = edge_types (dead in reference) */
    const int*   cell_mask = (const int*)d_in[3];
    const float* kernelW   = (const float*)d_in[4];
    const float* rkernel   = (const float*)d_in[5];
    const float* bias      = (const float*)d_in[6];
    const float* v         = (const float*)d_in[7];
    /* d_in[8] = edge_emb (dead in reference) */
    float* out = (float*)d_out;
    (void)in_sizes; (void)n_in; (void)out_size;

    cudaFuncSetAttribute(gemm_tc, cudaFuncAttributeMaxDynamicSharedMemorySize, DSMEM_BYTES);

    prep_W<<<480, 256>>>(kernelW, rkernel);
    gemm_tc<<<dim3(NTP_N, MT_N, NZ), 256, DSMEM_BYTES>>>(
        inputs, states, kernelW, rkernel, bias);
    fuse_kernel<<<B_ROWS / 4, 256>>>(states, cell_mask, v, out);
}